// round 1
// baseline (speedup 1.0000x reference)
#include <cuda_runtime.h>
#include <cuda_bf16.h>

#define BEV_H 512
#define BEV_W 512
#define BEV_C 64
#define HW (BEV_H * BEV_W)   // 262144 = 2^18

// Scratch: last-writer pillar index per BEV cell. Sized for up to 8 batches.
__device__ int g_last[8 * HW];
// Zero row for invalid cells (device globals are zero-initialized; never written).
__device__ float g_zero[BEV_C];

__global__ void bev_init_kernel(int n4) {
    int i = blockIdx.x * blockDim.x + threadIdx.x;
    if (i < n4) {
        reinterpret_cast<int4*>(g_last)[i] = make_int4(-1, -1, -1, -1);
    }
}

__global__ void bev_scatter_kernel(const int* __restrict__ coords, int P) {
    int i = blockIdx.x * blockDim.x + threadIdx.x;
    if (i >= P) return;
    int b = coords[3 * i + 0];
    int r = coords[3 * i + 1];
    int c = coords[3 * i + 2];
    r = min(max(r, 0), BEV_H - 1);
    c = min(max(c, 0), BEV_W - 1);
    atomicMax(&g_last[b * HW + r * BEV_W + c], i);
}

__global__ void __launch_bounds__(256) bev_gather_kernel(
    const float* __restrict__ feats,
    float* __restrict__ out,
    int ncells) {
    int cell = blockIdx.x * blockDim.x + threadIdx.x;
    if (cell >= ncells) return;

    int b   = cell >> 18;          // cell / HW
    int pos = cell & (HW - 1);     // cell % HW

    int last = g_last[cell];
    // Redirect empty cells to the zero row: keeps the warp convergent so every
    // store below is a fully coalesced 128B warp transaction, and the zero-row
    // loads broadcast (single L1 wavefront).
    const float4* row = reinterpret_cast<const float4*>(
        last >= 0 ? feats + (size_t)last * BEV_C : g_zero);

    float* o = out + (size_t)b * BEV_C * HW + pos;
#pragma unroll
    for (int i = 0; i < BEV_C / 4; i++) {
        float4 v = __ldg(row + i);
        o[(size_t)(4 * i + 0) * HW] = v.x;
        o[(size_t)(4 * i + 1) * HW] = v.y;
        o[(size_t)(4 * i + 2) * HW] = v.z;
        o[(size_t)(4 * i + 3) * HW] = v.w;
    }
}

extern "C" void kernel_launch(void* const* d_in, const int* in_sizes, int n_in,
                              void* d_out, int out_size) {
    const float* feats  = (const float*)d_in[0];   // (P, 64) float32
    const int*   coords = (const int*)d_in[1];     // (P, 3) int32
    float*       out    = (float*)d_out;           // (B, 64, 512, 512) float32

    int P = in_sizes[0] / BEV_C;
    int B = out_size / (BEV_C * HW);
    if (B > 8) B = 8;  // scratch bound (setup uses B=4)
    int ncells = B * HW;

    // 1) init last-index grid to -1 (int4-vectorized)
    int n4 = ncells / 4;
    bev_init_kernel<<<(n4 + 255) / 256, 256>>>(n4);

    // 2) scatter: last-occurrence-wins via atomicMax on pillar index
    bev_scatter_kernel<<<(P + 255) / 256, 256>>>(coords, P);

    // 3) gather + transpose to (B, C, H, W), zero-filling empty cells
    bev_gather_kernel<<<(ncells + 255) / 256, 256>>>(feats, out, ncells);
}